// round 11
// baseline (speedup 1.0000x reference)
#include <cuda_runtime.h>

#define NN 50000
#define EE 800000
#define DD 128

// ---------------- scratch (static __device__ arrays; no allocation) ----------------
__device__ __align__(16) float g_agg [(size_t)NN * DD];
__device__ __align__(16) float g_buf0[(size_t)NN * DD];
__device__ __align__(16) float g_buf1[(size_t)NN * DD];
__device__ float g_outnorm[NN];
__device__ float g_innorm [NN];
__device__ int   g_indeg  [NN];
__device__ int   g_outdeg [NN];
__device__ int   g_cursor [NN];
__device__ int   g_rowptr [NN + 1];
__device__ int   g_srcsorted[EE];

#define SCAN_T 512
#define SCAN_I 4
#define SCAN_CHUNK (SCAN_T * SCAN_I)                       // 2048
#define SCAN_B ((NN + SCAN_CHUNK - 1) / SCAN_CHUNK)        // 25
__device__ int g_blockSums[SCAN_B];
__device__ int g_blockOffs[SCAN_B];

// ---------------- f32x2 packed-FMA helpers ----------------
__device__ __forceinline__ unsigned long long pack2(float x, float y) {
    unsigned long long r;
    asm("mov.b64 %0, {%1, %2};" : "=l"(r) : "f"(x), "f"(y));
    return r;
}
__device__ __forceinline__ unsigned long long bcast2(float x) {
    unsigned long long r;
    asm("mov.b64 %0, {%1, %1};" : "=l"(r) : "f"(x));
    return r;
}
__device__ __forceinline__ void ffma2(unsigned long long& d,
                                      unsigned long long a, unsigned long long b) {
    asm("fma.rn.f32x2 %0, %1, %2, %0;" : "+l"(d) : "l"(a), "l"(b));
}
__device__ __forceinline__ void unpack2(unsigned long long v, float& x, float& y) {
    asm("mov.b64 {%0, %1}, %2;" : "=f"(x), "=f"(y) : "l"(v));
}

// ---------------- thin streaming copy: 1 block/SM, deep MLP, evict-first ----------
#define CPY_UNROLL 16
__global__ void copy_kernel(const float4* __restrict__ src, float4* __restrict__ dst,
                            int n4) {
    int stride = gridDim.x * blockDim.x;
    int i = blockIdx.x * blockDim.x + threadIdx.x;
    int span = stride * CPY_UNROLL;
    for (; i + (CPY_UNROLL - 1) * stride < n4; i += span) {
        float4 v[CPY_UNROLL];
        #pragma unroll
        for (int u = 0; u < CPY_UNROLL; u++) v[u] = __ldcs(src + i + u * stride);
        #pragma unroll
        for (int u = 0; u < CPY_UNROLL; u++) __stcs(dst + i + u * stride, v[u]);
    }
    for (; i < n4; i += stride) __stcs(dst + i, __ldcs(src + i));
}

// ---------------- graph preprocessing ----------------
__global__ void zero_kernel() {
    int i = blockIdx.x * blockDim.x + threadIdx.x;
    if (i < NN) { g_indeg[i] = 0; g_outdeg[i] = 0; g_cursor[i] = 0; }
}

__global__ void deg_kernel(const int* __restrict__ src, const int* __restrict__ dst) {
    int i = blockIdx.x * blockDim.x + threadIdx.x;
    if (i < EE) {
        atomicAdd(&g_outdeg[src[i]], 1);
        atomicAdd(&g_indeg [dst[i]], 1);
    }
}

__global__ void norm_kernel() {
    int i = blockIdx.x * blockDim.x + threadIdx.x;
    if (i < NN) {
        g_outnorm[i] = rsqrtf(fmaxf((float)g_outdeg[i], 1.0f));
        g_innorm [i] = rsqrtf(fmaxf((float)g_indeg [i], 1.0f));
    }
}

// ---- two-level scan ----
__global__ void scanA_kernel() {
    __shared__ int warpSums[SCAN_T / 32];
    int b   = blockIdx.x;
    int tid = threadIdx.x;
    int lane = tid & 31, wid = tid >> 5;
    int base = b * SCAN_CHUNK + tid * SCAN_I;

    int v[SCAN_I];
    int s = 0;
    #pragma unroll
    for (int j = 0; j < SCAN_I; j++) {
        int i = base + j;
        v[j] = (i < NN) ? g_indeg[i] : 0;
        s += v[j];
    }
    int incl = s;
    #pragma unroll
    for (int off = 1; off < 32; off <<= 1) {
        int t = __shfl_up_sync(0xffffffff, incl, off);
        if (lane >= off) incl += t;
    }
    if (lane == 31) warpSums[wid] = incl;
    __syncthreads();
    if (wid == 0) {
        int ws = (lane < SCAN_T / 32) ? warpSums[lane] : 0;
        #pragma unroll
        for (int off = 1; off < SCAN_T / 32; off <<= 1) {
            int t = __shfl_up_sync(0xffffffff, ws, off);
            if (lane >= off) ws += t;
        }
        if (lane < SCAN_T / 32) warpSums[lane] = ws;
    }
    __syncthreads();
    int warpOff = (wid > 0) ? warpSums[wid - 1] : 0;
    int run     = warpOff + incl - s;
    #pragma unroll
    for (int j = 0; j < SCAN_I; j++) {
        int i = base + j;
        if (i < NN) g_rowptr[i] = run;
        run += v[j];
    }
    if (tid == SCAN_T - 1) g_blockSums[b] = warpSums[SCAN_T / 32 - 1];
}

__global__ void scanB_kernel() {
    int lane = threadIdx.x;
    int v = (lane < SCAN_B) ? g_blockSums[lane] : 0;
    int incl = v;
    #pragma unroll
    for (int off = 1; off < 32; off <<= 1) {
        int t = __shfl_up_sync(0xffffffff, incl, off);
        if (lane >= off) incl += t;
    }
    if (lane < SCAN_B) g_blockOffs[lane] = incl - v;
    if (lane == 31) g_rowptr[NN] = incl;
}

__global__ void scanC_kernel() {
    int b = blockIdx.x;
    int off = g_blockOffs[b];
    if (off == 0) return;
    int base = b * SCAN_CHUNK + threadIdx.x * SCAN_I;
    #pragma unroll
    for (int j = 0; j < SCAN_I; j++) {
        int i = base + j;
        if (i < NN) g_rowptr[i] += off;
    }
}

__global__ void scatter_kernel(const int* __restrict__ src, const int* __restrict__ dst) {
    int i = blockIdx.x * blockDim.x + threadIdx.x;
    if (i < EE) {
        int d = dst[i];
        int pos = g_rowptr[d] + atomicAdd(&g_cursor[d], 1);
        g_srcsorted[pos] = src[i];
    }
}

// ---------------- aggregation: one warp per node, CSR, 4-way unrolled ----------------
__global__ void agg_kernel(const float* __restrict__ h) {
    int gw = (blockIdx.x * blockDim.x + threadIdx.x) >> 5;
    if (gw >= NN) return;
    int lane = threadIdx.x & 31;
    int beg = g_rowptr[gw], end = g_rowptr[gw + 1];

    float ax = 0.f, ay = 0.f, az = 0.f, aw = 0.f;
    int e = beg;
    for (; e + 4 <= end; e += 4) {
        int s0 = g_srcsorted[e],     s1 = g_srcsorted[e + 1];
        int s2 = g_srcsorted[e + 2], s3 = g_srcsorted[e + 3];
        float w0 = g_outnorm[s0], w1 = g_outnorm[s1];
        float w2 = g_outnorm[s2], w3 = g_outnorm[s3];
        float4 x0 = *(const float4*)(h + (size_t)s0 * DD + lane * 4);
        float4 x1 = *(const float4*)(h + (size_t)s1 * DD + lane * 4);
        float4 x2 = *(const float4*)(h + (size_t)s2 * DD + lane * 4);
        float4 x3 = *(const float4*)(h + (size_t)s3 * DD + lane * 4);
        ax += w0 * x0.x; ay += w0 * x0.y; az += w0 * x0.z; aw += w0 * x0.w;
        ax += w1 * x1.x; ay += w1 * x1.y; az += w1 * x1.z; aw += w1 * x1.w;
        ax += w2 * x2.x; ay += w2 * x2.y; az += w2 * x2.z; aw += w2 * x2.w;
        ax += w3 * x3.x; ay += w3 * x3.y; az += w3 * x3.z; aw += w3 * x3.w;
    }
    for (; e < end; e++) {
        int s0 = g_srcsorted[e];
        float w0 = g_outnorm[s0];
        float4 x0 = *(const float4*)(h + (size_t)s0 * DD + lane * 4);
        ax += w0 * x0.x; ay += w0 * x0.y; az += w0 * x0.z; aw += w0 * x0.w;
    }
    float s = g_innorm[gw];
    float4 r = make_float4(ax * s, ay * s, az * s, aw * s);
    *(float4*)(g_agg + (size_t)gw * DD + lane * 4) = r;
}

// ---------------- SGEMM: C[M,128] = A[M,128] @ W[128,128] + b, optional relu ----------
// Block tile 128x128, 512 threads (16 warps), 4x8 register microkernel, FFMA2.
#define LDSA 132

__global__ void gemm_kernel(const float* __restrict__ A, const float* __restrict__ W,
                            const float* __restrict__ bias, float* __restrict__ C,
                            int M, int doRelu) {
    extern __shared__ float smem[];
    float* As = smem;               // k-major: As[k*LDSA + m]
    float* Bs = smem + 128 * LDSA;  // row-major: Bs[k*128 + n]
    int tid = threadIdx.x;
    int blockM = blockIdx.x * 128;

    // Load A tile transposed (k-major): 512 threads, each 8 float4 (quarter row)
    {
        int m  = tid >> 2;
        int kh = (tid & 3) * 32;
        int gm = blockM + m;
        bool valid = gm < M;
        const float4* arow = (const float4*)(A + (size_t)gm * DD + kh);
        #pragma unroll
        for (int j = 0; j < 8; j++) {
            float4 v = valid ? arow[j] : make_float4(0.f, 0.f, 0.f, 0.f);
            int k = kh + j * 4;
            As[(k + 0) * LDSA + m] = v.x;
            As[(k + 1) * LDSA + m] = v.y;
            As[(k + 2) * LDSA + m] = v.z;
            As[(k + 3) * LDSA + m] = v.w;
        }
    }
    // Load W tile (512 threads, coalesced)
    {
        int nq = tid & 31;
        int kg = tid >> 5;   // 0..15
        #pragma unroll
        for (int r = 0; r < 8; r++) {
            int k = kg * 8 + r;
            *(float4*)(Bs + k * 128 + nq * 4) = *(const float4*)(W + k * 128 + nq * 4);
        }
    }
    __syncthreads();

    // 512 threads: tx in [0,16) -> 8 n-cols, ty in [0,32) -> 4 m-rows
    int tx = tid & 15, ty = tid >> 4;
    int mBase = ty * 4, nBase = tx * 8;

    unsigned long long acc[4][4];
    const unsigned long long z = pack2(0.f, 0.f);
    #pragma unroll
    for (int i = 0; i < 4; i++)
        #pragma unroll
        for (int jp = 0; jp < 4; jp++) acc[i][jp] = z;

    #pragma unroll 8
    for (int k = 0; k < 128; k++) {
        float4 a0 = *(const float4*)(As + k * LDSA + mBase);
        float4 b0 = *(const float4*)(Bs + k * 128 + nBase);
        float4 b1 = *(const float4*)(Bs + k * 128 + nBase + 4);

        unsigned long long bp[4];
        bp[0] = pack2(b0.x, b0.y);
        bp[1] = pack2(b0.z, b0.w);
        bp[2] = pack2(b1.x, b1.y);
        bp[3] = pack2(b1.z, b1.w);

        float a[4] = {a0.x, a0.y, a0.z, a0.w};
        #pragma unroll
        for (int i = 0; i < 4; i++) {
            unsigned long long aa = bcast2(a[i]);
            #pragma unroll
            for (int jp = 0; jp < 4; jp++)
                ffma2(acc[i][jp], aa, bp[jp]);
        }
    }

    float bv[8];
    #pragma unroll
    for (int j = 0; j < 8; j++) bv[j] = bias[nBase + j];

    #pragma unroll
    for (int i = 0; i < 4; i++) {
        int gm = blockM + mBase + i;
        if (gm < M) {
            float o[8];
            #pragma unroll
            for (int jp = 0; jp < 4; jp++) {
                float x, y;
                unpack2(acc[i][jp], x, y);
                o[jp * 2]     = x + bv[jp * 2];
                o[jp * 2 + 1] = y + bv[jp * 2 + 1];
            }
            if (doRelu) {
                #pragma unroll
                for (int j = 0; j < 8; j++) o[j] = fmaxf(o[j], 0.f);
            }
            *(float4*)(C + (size_t)gm * DD + nBase)     = make_float4(o[0], o[1], o[2], o[3]);
            *(float4*)(C + (size_t)gm * DD + nBase + 4) = make_float4(o[4], o[5], o[6], o[7]);
        }
    }
}

// ---------------- launch ----------------
extern "C" void kernel_launch(void* const* d_in, const int* in_sizes, int n_in,
                              void* d_out, int out_size) {
    const float* h   = (const float*)d_in[0];
    const float* e   = (const float*)d_in[1];
    const int*   src = (const int*)  d_in[2];
    const int*   dst = (const int*)  d_in[3];
    const float* Ws  = (const float*)d_in[4];
    const float* bs  = (const float*)d_in[5];
    float* out = (float*)d_out;

    static cudaStream_t s_side = nullptr;
    static cudaEvent_t  s_fork = nullptr, s_join = nullptr;
    if (!s_side) {
        cudaStreamCreateWithFlags(&s_side, cudaStreamNonBlocking);
        cudaEventCreateWithFlags(&s_fork, cudaEventDisableTiming);
        cudaEventCreateWithFlags(&s_join, cudaEventDisableTiming);
    }

    size_t eElems = (size_t)in_sizes[1];
    int n4 = (int)(eElems / 4);
    const int copyBlocks = 148;          // thin: ~1 block/SM
    bool overlapped = false;
    if (s_side && s_fork && s_join) {
        if (cudaEventRecord(s_fork, 0) == cudaSuccess &&
            cudaStreamWaitEvent(s_side, s_fork, 0) == cudaSuccess) {
            copy_kernel<<<copyBlocks, 256, 0, s_side>>>(
                (const float4*)e, (float4*)(out + (size_t)NN * DD), n4);
            cudaEventRecord(s_join, s_side);
            overlapped = true;
        }
    }
    if (!overlapped) {
        copy_kernel<<<copyBlocks * 6, 256>>>(
            (const float4*)e, (float4*)(out + (size_t)NN * DD), n4);
    }

    const int nb = (NN + 255) / 256;
    const int eb = (EE + 255) / 256;
    zero_kernel<<<nb, 256>>>();
    deg_kernel<<<eb, 256>>>(src, dst);
    norm_kernel<<<nb, 256>>>();
    scanA_kernel<<<SCAN_B, SCAN_T>>>();
    scanB_kernel<<<1, 32>>>();
    scanC_kernel<<<SCAN_B, SCAN_T>>>();
    scatter_kernel<<<eb, 256>>>(src, dst);

    float *agg, *b0, *b1;
    cudaGetSymbolAddress((void**)&agg, g_agg);
    cudaGetSymbolAddress((void**)&b0,  g_buf0);
    cudaGetSymbolAddress((void**)&b1,  g_buf1);

    const int SMEM = (128 * LDSA + 128 * 128) * (int)sizeof(float);
    cudaFuncSetAttribute(gemm_kernel, cudaFuncAttributeMaxDynamicSharedMemorySize, SMEM);

    const int aggBlocks  = (NN * 32 + 255) / 256;
    const int gemmBlocks = (NN + 127) / 128;

    // layer 0
    agg_kernel<<<aggBlocks, 256>>>(h);
    gemm_kernel<<<gemmBlocks, 512, SMEM>>>(agg, Ws,               bs,          b0, NN, 1);
    // layer 1
    agg_kernel<<<aggBlocks, 256>>>(b0);
    gemm_kernel<<<gemmBlocks, 512, SMEM>>>(agg, Ws + DD * DD,     bs + DD,     b1, NN, 1);
    // layer 2 (no relu), write straight into d_out
    agg_kernel<<<aggBlocks, 256>>>(b1);
    gemm_kernel<<<gemmBlocks, 512, SMEM>>>(agg, Ws + 2 * DD * DD, bs + 2 * DD, out, NN, 0);

    if (overlapped) cudaStreamWaitEvent(0, s_join, 0);
}

// round 12
// speedup vs baseline: 1.2098x; 1.2098x over previous
#include <cuda_runtime.h>

#define NN 50000
#define EE 800000
#define DD 128

// ---------------- scratch (static __device__ arrays; no allocation) ----------------
__device__ __align__(16) float g_agg [(size_t)NN * DD];
__device__ __align__(16) float g_buf0[(size_t)NN * DD];
__device__ __align__(16) float g_buf1[(size_t)NN * DD];
__device__ float g_outnorm[NN];
__device__ float g_innorm [NN];
__device__ int   g_indeg  [NN];
__device__ int   g_outdeg [NN];
__device__ int   g_cursor [NN];
__device__ int   g_rowptr [NN + 1];
__device__ int   g_srcsorted[EE];

#define SCAN_T 512
#define SCAN_I 4
#define SCAN_CHUNK (SCAN_T * SCAN_I)                       // 2048
#define SCAN_B ((NN + SCAN_CHUNK - 1) / SCAN_CHUNK)        // 25
__device__ int g_blockSums[SCAN_B];
__device__ int g_blockOffs[SCAN_B];

// ---------------- f32x2 packed-FMA helpers ----------------
__device__ __forceinline__ unsigned long long pack2(float x, float y) {
    unsigned long long r;
    asm("mov.b64 %0, {%1, %2};" : "=l"(r) : "f"(x), "f"(y));
    return r;
}
__device__ __forceinline__ unsigned long long bcast2(float x) {
    unsigned long long r;
    asm("mov.b64 %0, {%1, %1};" : "=l"(r) : "f"(x));
    return r;
}
__device__ __forceinline__ void ffma2(unsigned long long& d,
                                      unsigned long long a, unsigned long long b) {
    asm("fma.rn.f32x2 %0, %1, %2, %0;" : "+l"(d) : "l"(a), "l"(b));
}
__device__ __forceinline__ void unpack2(unsigned long long v, float& x, float& y) {
    asm("mov.b64 {%0, %1}, %2;" : "=f"(x), "=f"(y) : "l"(v));
}

// ---------------- thin streaming copy: 1 block/SM, deep MLP, evict-first ----------
#define CPY_UNROLL 16
__global__ void copy_kernel(const float4* __restrict__ src, float4* __restrict__ dst,
                            int n4) {
    int stride = gridDim.x * blockDim.x;
    int i = blockIdx.x * blockDim.x + threadIdx.x;
    int span = stride * CPY_UNROLL;
    for (; i + (CPY_UNROLL - 1) * stride < n4; i += span) {
        float4 v[CPY_UNROLL];
        #pragma unroll
        for (int u = 0; u < CPY_UNROLL; u++) v[u] = __ldcs(src + i + u * stride);
        #pragma unroll
        for (int u = 0; u < CPY_UNROLL; u++) __stcs(dst + i + u * stride, v[u]);
    }
    for (; i < n4; i += stride) __stcs(dst + i, __ldcs(src + i));
}

// ---------------- graph preprocessing ----------------
__global__ void zero_kernel() {
    int i = blockIdx.x * blockDim.x + threadIdx.x;
    if (i < NN) { g_indeg[i] = 0; g_outdeg[i] = 0; g_cursor[i] = 0; }
}

__global__ void deg_kernel(const int* __restrict__ src, const int* __restrict__ dst) {
    int i = blockIdx.x * blockDim.x + threadIdx.x;
    if (i < EE) {
        atomicAdd(&g_outdeg[src[i]], 1);
        atomicAdd(&g_indeg [dst[i]], 1);
    }
}

__global__ void norm_kernel() {
    int i = blockIdx.x * blockDim.x + threadIdx.x;
    if (i < NN) {
        g_outnorm[i] = rsqrtf(fmaxf((float)g_outdeg[i], 1.0f));
        g_innorm [i] = rsqrtf(fmaxf((float)g_indeg [i], 1.0f));
    }
}

// ---- two-level scan ----
__global__ void scanA_kernel() {
    __shared__ int warpSums[SCAN_T / 32];
    int b   = blockIdx.x;
    int tid = threadIdx.x;
    int lane = tid & 31, wid = tid >> 5;
    int base = b * SCAN_CHUNK + tid * SCAN_I;

    int v[SCAN_I];
    int s = 0;
    #pragma unroll
    for (int j = 0; j < SCAN_I; j++) {
        int i = base + j;
        v[j] = (i < NN) ? g_indeg[i] : 0;
        s += v[j];
    }
    int incl = s;
    #pragma unroll
    for (int off = 1; off < 32; off <<= 1) {
        int t = __shfl_up_sync(0xffffffff, incl, off);
        if (lane >= off) incl += t;
    }
    if (lane == 31) warpSums[wid] = incl;
    __syncthreads();
    if (wid == 0) {
        int ws = (lane < SCAN_T / 32) ? warpSums[lane] : 0;
        #pragma unroll
        for (int off = 1; off < SCAN_T / 32; off <<= 1) {
            int t = __shfl_up_sync(0xffffffff, ws, off);
            if (lane >= off) ws += t;
        }
        if (lane < SCAN_T / 32) warpSums[lane] = ws;
    }
    __syncthreads();
    int warpOff = (wid > 0) ? warpSums[wid - 1] : 0;
    int run     = warpOff + incl - s;
    #pragma unroll
    for (int j = 0; j < SCAN_I; j++) {
        int i = base + j;
        if (i < NN) g_rowptr[i] = run;
        run += v[j];
    }
    if (tid == SCAN_T - 1) g_blockSums[b] = warpSums[SCAN_T / 32 - 1];
}

__global__ void scanB_kernel() {
    int lane = threadIdx.x;
    int v = (lane < SCAN_B) ? g_blockSums[lane] : 0;
    int incl = v;
    #pragma unroll
    for (int off = 1; off < 32; off <<= 1) {
        int t = __shfl_up_sync(0xffffffff, incl, off);
        if (lane >= off) incl += t;
    }
    if (lane < SCAN_B) g_blockOffs[lane] = incl - v;
    if (lane == 31) g_rowptr[NN] = incl;
}

__global__ void scanC_kernel() {
    int b = blockIdx.x;
    int off = g_blockOffs[b];
    if (off == 0) return;
    int base = b * SCAN_CHUNK + threadIdx.x * SCAN_I;
    #pragma unroll
    for (int j = 0; j < SCAN_I; j++) {
        int i = base + j;
        if (i < NN) g_rowptr[i] += off;
    }
}

__global__ void scatter_kernel(const int* __restrict__ src, const int* __restrict__ dst) {
    int i = blockIdx.x * blockDim.x + threadIdx.x;
    if (i < EE) {
        int d = dst[i];
        int pos = g_rowptr[d] + atomicAdd(&g_cursor[d], 1);
        g_srcsorted[pos] = src[i];
    }
}

// ---------------- aggregation: one warp per node, CSR, 4-way unrolled ----------------
__device__ __forceinline__ float4 ldcg4(const float* p) {
    return __ldcg((const float4*)p);
}

__global__ void agg_kernel(const float* __restrict__ h) {
    int gw = (blockIdx.x * blockDim.x + threadIdx.x) >> 5;
    if (gw >= NN) return;
    int lane = threadIdx.x & 31;
    int beg = g_rowptr[gw], end = g_rowptr[gw + 1];

    float ax = 0.f, ay = 0.f, az = 0.f, aw = 0.f;
    int e = beg;
    for (; e + 4 <= end; e += 4) {
        int s0 = g_srcsorted[e],     s1 = g_srcsorted[e + 1];
        int s2 = g_srcsorted[e + 2], s3 = g_srcsorted[e + 3];
        float w0 = g_outnorm[s0], w1 = g_outnorm[s1];
        float w2 = g_outnorm[s2], w3 = g_outnorm[s3];
        float4 x0 = ldcg4(h + (size_t)s0 * DD + lane * 4);
        float4 x1 = ldcg4(h + (size_t)s1 * DD + lane * 4);
        float4 x2 = ldcg4(h + (size_t)s2 * DD + lane * 4);
        float4 x3 = ldcg4(h + (size_t)s3 * DD + lane * 4);
        ax += w0 * x0.x; ay += w0 * x0.y; az += w0 * x0.z; aw += w0 * x0.w;
        ax += w1 * x1.x; ay += w1 * x1.y; az += w1 * x1.z; aw += w1 * x1.w;
        ax += w2 * x2.x; ay += w2 * x2.y; az += w2 * x2.z; aw += w2 * x2.w;
        ax += w3 * x3.x; ay += w3 * x3.y; az += w3 * x3.z; aw += w3 * x3.w;
    }
    for (; e < end; e++) {
        int s0 = g_srcsorted[e];
        float w0 = g_outnorm[s0];
        float4 x0 = ldcg4(h + (size_t)s0 * DD + lane * 4);
        ax += w0 * x0.x; ay += w0 * x0.y; az += w0 * x0.z; aw += w0 * x0.w;
    }
    float s = g_innorm[gw];
    float4 r = make_float4(ax * s, ay * s, az * s, aw * s);
    *(float4*)(g_agg + (size_t)gw * DD + lane * 4) = r;
}

// ---------------- persistent SGEMM: W loaded once per block, loop over M tiles -------
// Block tile 128x128, 256 threads, 8x8 register microkernel, FFMA2.
#define LDSA 132
#define GEMM_GRID 148

__global__ void gemm_kernel(const float* __restrict__ A, const float* __restrict__ W,
                            const float* __restrict__ bias, float* __restrict__ C,
                            int M, int doRelu) {
    extern __shared__ float smem[];
    float* As = smem;               // k-major: As[k*LDSA + m]
    float* Bs = smem + 128 * LDSA;  // row-major: Bs[k*128 + n]
    int tid = threadIdx.x;

    // ---- load W tile ONCE ----
    {
        int nq = tid & 31;
        int kg = tid >> 5;
        #pragma unroll
        for (int r = 0; r < 16; r++) {
            int k = kg * 16 + r;
            *(float4*)(Bs + k * 128 + nq * 4) = *(const float4*)(W + k * 128 + nq * 4);
        }
    }

    int tx = tid & 15, ty = tid >> 4;
    int mBase = ty * 8, nBase = tx * 8;

    float bv[8];
    #pragma unroll
    for (int j = 0; j < 8; j++) bv[j] = bias[nBase + j];

    const int numTiles = (M + 127) / 128;
    for (int tile = blockIdx.x; tile < numTiles; tile += gridDim.x) {
        int blockM = tile * 128;

        __syncthreads();   // previous tile's math done before As overwrite (and Bs ready)
        // ---- load A tile transposed (k-major) ----
        {
            int m  = tid >> 1;
            int kh = (tid & 1) * 64;
            int gm = blockM + m;
            bool valid = gm < M;
            const float4* arow = (const float4*)(A + (size_t)gm * DD + kh);
            #pragma unroll
            for (int j = 0; j < 16; j++) {
                float4 v = valid ? arow[j] : make_float4(0.f, 0.f, 0.f, 0.f);
                int k = kh + j * 4;
                As[(k + 0) * LDSA + m] = v.x;
                As[(k + 1) * LDSA + m] = v.y;
                As[(k + 2) * LDSA + m] = v.z;
                As[(k + 3) * LDSA + m] = v.w;
            }
        }
        __syncthreads();

        unsigned long long acc[8][4];
        const unsigned long long z = pack2(0.f, 0.f);
        #pragma unroll
        for (int i = 0; i < 8; i++)
            #pragma unroll
            for (int jp = 0; jp < 4; jp++) acc[i][jp] = z;

        #pragma unroll 4
        for (int k = 0; k < 128; k++) {
            float4 a0 = *(const float4*)(As + k * LDSA + mBase);
            float4 a1 = *(const float4*)(As + k * LDSA + mBase + 4);
            float4 b0 = *(const float4*)(Bs + k * 128 + nBase);
            float4 b1 = *(const float4*)(Bs + k * 128 + nBase + 4);

            unsigned long long bp[4];
            bp[0] = pack2(b0.x, b0.y);
            bp[1] = pack2(b0.z, b0.w);
            bp[2] = pack2(b1.x, b1.y);
            bp[3] = pack2(b1.z, b1.w);

            float a[8] = {a0.x, a0.y, a0.z, a0.w, a1.x, a1.y, a1.z, a1.w};
            #pragma unroll
            for (int i = 0; i < 8; i++) {
                unsigned long long aa = bcast2(a[i]);
                #pragma unroll
                for (int jp = 0; jp < 4; jp++)
                    ffma2(acc[i][jp], aa, bp[jp]);
            }
        }

        #pragma unroll
        for (int i = 0; i < 8; i++) {
            int gm = blockM + mBase + i;
            if (gm < M) {
                float o[8];
                #pragma unroll
                for (int jp = 0; jp < 4; jp++) {
                    float x, y;
                    unpack2(acc[i][jp], x, y);
                    o[jp * 2]     = x + bv[jp * 2];
                    o[jp * 2 + 1] = y + bv[jp * 2 + 1];
                }
                if (doRelu) {
                    #pragma unroll
                    for (int j = 0; j < 8; j++) o[j] = fmaxf(o[j], 0.f);
                }
                *(float4*)(C + (size_t)gm * DD + nBase)     = make_float4(o[0], o[1], o[2], o[3]);
                *(float4*)(C + (size_t)gm * DD + nBase + 4) = make_float4(o[4], o[5], o[6], o[7]);
            }
        }
    }
}

// ---------------- launch ----------------
extern "C" void kernel_launch(void* const* d_in, const int* in_sizes, int n_in,
                              void* d_out, int out_size) {
    const float* h   = (const float*)d_in[0];
    const float* e   = (const float*)d_in[1];
    const int*   src = (const int*)  d_in[2];
    const int*   dst = (const int*)  d_in[3];
    const float* Ws  = (const float*)d_in[4];
    const float* bs  = (const float*)d_in[5];
    float* out = (float*)d_out;

    static cudaStream_t s_side = nullptr;
    static cudaEvent_t  s_fork = nullptr, s_join = nullptr;
    if (!s_side) {
        cudaStreamCreateWithFlags(&s_side, cudaStreamNonBlocking);
        cudaEventCreateWithFlags(&s_fork, cudaEventDisableTiming);
        cudaEventCreateWithFlags(&s_join, cudaEventDisableTiming);
    }

    size_t eElems = (size_t)in_sizes[1];
    int n4 = (int)(eElems / 4);
    const int copyBlocks = 148;          // thin: ~1 block/SM
    bool overlapped = false;
    if (s_side && s_fork && s_join) {
        if (cudaEventRecord(s_fork, 0) == cudaSuccess &&
            cudaStreamWaitEvent(s_side, s_fork, 0) == cudaSuccess) {
            copy_kernel<<<copyBlocks, 256, 0, s_side>>>(
                (const float4*)e, (float4*)(out + (size_t)NN * DD), n4);
            cudaEventRecord(s_join, s_side);
            overlapped = true;
        }
    }
    if (!overlapped) {
        copy_kernel<<<copyBlocks * 6, 256>>>(
            (const float4*)e, (float4*)(out + (size_t)NN * DD), n4);
    }

    const int nb = (NN + 255) / 256;
    const int eb = (EE + 255) / 256;
    zero_kernel<<<nb, 256>>>();
    deg_kernel<<<eb, 256>>>(src, dst);
    norm_kernel<<<nb, 256>>>();
    scanA_kernel<<<SCAN_B, SCAN_T>>>();
    scanB_kernel<<<1, 32>>>();
    scanC_kernel<<<SCAN_B, SCAN_T>>>();
    scatter_kernel<<<eb, 256>>>(src, dst);

    float *agg, *b0, *b1;
    cudaGetSymbolAddress((void**)&agg, g_agg);
    cudaGetSymbolAddress((void**)&b0,  g_buf0);
    cudaGetSymbolAddress((void**)&b1,  g_buf1);

    const int SMEM = (128 * LDSA + 128 * 128) * (int)sizeof(float);
    cudaFuncSetAttribute(gemm_kernel, cudaFuncAttributeMaxDynamicSharedMemorySize, SMEM);

    const int aggBlocks = (NN * 32 + 255) / 256;

    // layer 0
    agg_kernel<<<aggBlocks, 256>>>(h);
    gemm_kernel<<<GEMM_GRID, 256, SMEM>>>(agg, Ws,               bs,          b0, NN, 1);
    // layer 1
    agg_kernel<<<aggBlocks, 256>>>(b0);
    gemm_kernel<<<GEMM_GRID, 256, SMEM>>>(agg, Ws + DD * DD,     bs + DD,     b1, NN, 1);
    // layer 2 (no relu), write straight into d_out
    agg_kernel<<<aggBlocks, 256>>>(b1);
    gemm_kernel<<<GEMM_GRID, 256, SMEM>>>(agg, Ws + 2 * DD * DD, bs + 2 * DD, out, NN, 0);

    if (overlapped) cudaStreamWaitEvent(0, s_join, 0);
}

// round 14
// speedup vs baseline: 1.2956x; 1.0709x over previous
#include <cuda_runtime.h>
#include <cuda_fp16.h>

#define NN 50000
#define EE 800000
#define DD 128

// ---------------- scratch (static __device__ arrays; no allocation) ----------------
__device__ __align__(16) float  g_agg [(size_t)NN * DD];
__device__ __align__(16) __half g_h16 [(size_t)NN * DD];   // fp16 copy of layer input
__device__ __align__(16) __half g_b016[(size_t)NN * DD];
__device__ __align__(16) __half g_b116[(size_t)NN * DD];
__device__ float g_outnorm[NN];
__device__ float g_innorm [NN];
__device__ int   g_indeg  [NN];
__device__ int   g_outdeg [NN];
__device__ int   g_cursor [NN];
__device__ int   g_rowptr [NN + 1];
__device__ int   g_srcsorted[EE];

#define SCAN_T 512
#define SCAN_I 4
#define SCAN_CHUNK (SCAN_T * SCAN_I)                       // 2048
#define SCAN_B ((NN + SCAN_CHUNK - 1) / SCAN_CHUNK)        // 25
__device__ int g_blockSums[SCAN_B];
__device__ int g_blockOffs[SCAN_B];

// ---------------- bit-punning helpers for half2 <-> uint ----------------
__device__ __forceinline__ unsigned h2_to_u(__half2 h) {
    return *reinterpret_cast<unsigned*>(&h);
}
__device__ __forceinline__ __half2 u_to_h2(unsigned u) {
    return *reinterpret_cast<__half2*>(&u);
}

// ---------------- f32x2 packed-FMA helpers ----------------
__device__ __forceinline__ unsigned long long pack2(float x, float y) {
    unsigned long long r;
    asm("mov.b64 %0, {%1, %2};" : "=l"(r) : "f"(x), "f"(y));
    return r;
}
__device__ __forceinline__ unsigned long long bcast2(float x) {
    unsigned long long r;
    asm("mov.b64 %0, {%1, %1};" : "=l"(r) : "f"(x));
    return r;
}
__device__ __forceinline__ void ffma2(unsigned long long& d,
                                      unsigned long long a, unsigned long long b) {
    asm("fma.rn.f32x2 %0, %1, %2, %0;" : "+l"(d) : "l"(a), "l"(b));
}
__device__ __forceinline__ void unpack2(unsigned long long v, float& x, float& y) {
    asm("mov.b64 {%0, %1}, %2;" : "=f"(x), "=f"(y) : "l"(v));
}

// ---------------- thin streaming copy: 1 block/SM, deep MLP, evict-first ----------
#define CPY_UNROLL 16
__global__ void copy_kernel(const float4* __restrict__ src, float4* __restrict__ dst,
                            int n4) {
    int stride = gridDim.x * blockDim.x;
    int i = blockIdx.x * blockDim.x + threadIdx.x;
    int span = stride * CPY_UNROLL;
    for (; i + (CPY_UNROLL - 1) * stride < n4; i += span) {
        float4 v[CPY_UNROLL];
        #pragma unroll
        for (int u = 0; u < CPY_UNROLL; u++) v[u] = __ldcs(src + i + u * stride);
        #pragma unroll
        for (int u = 0; u < CPY_UNROLL; u++) __stcs(dst + i + u * stride, v[u]);
    }
    for (; i < n4; i += stride) __stcs(dst + i, __ldcs(src + i));
}

// ---------------- fp32 -> fp16 convert (for layer-0 input) ----------------
__global__ void convert_kernel(const float* __restrict__ in, __half* __restrict__ out,
                               int n) {
    int i = (blockIdx.x * blockDim.x + threadIdx.x) * 4;
    if (i < n) {
        float4 v = *(const float4*)(in + i);
        __half2 h0 = __floats2half2_rn(v.x, v.y);
        __half2 h1 = __floats2half2_rn(v.z, v.w);
        *(uint2*)(out + i) = make_uint2(h2_to_u(h0), h2_to_u(h1));
    }
}

// ---------------- graph preprocessing ----------------
__global__ void zero_kernel() {
    int i = blockIdx.x * blockDim.x + threadIdx.x;
    if (i < NN) { g_indeg[i] = 0; g_outdeg[i] = 0; g_cursor[i] = 0; }
}

__global__ void deg_kernel(const int* __restrict__ src, const int* __restrict__ dst) {
    int i = blockIdx.x * blockDim.x + threadIdx.x;
    if (i < EE) {
        atomicAdd(&g_outdeg[src[i]], 1);
        atomicAdd(&g_indeg [dst[i]], 1);
    }
}

__global__ void norm_kernel() {
    int i = blockIdx.x * blockDim.x + threadIdx.x;
    if (i < NN) {
        g_outnorm[i] = rsqrtf(fmaxf((float)g_outdeg[i], 1.0f));
        g_innorm [i] = rsqrtf(fmaxf((float)g_indeg [i], 1.0f));
    }
}

// ---- two-level scan ----
__global__ void scanA_kernel() {
    __shared__ int warpSums[SCAN_T / 32];
    int b   = blockIdx.x;
    int tid = threadIdx.x;
    int lane = tid & 31, wid = tid >> 5;
    int base = b * SCAN_CHUNK + tid * SCAN_I;

    int v[SCAN_I];
    int s = 0;
    #pragma unroll
    for (int j = 0; j < SCAN_I; j++) {
        int i = base + j;
        v[j] = (i < NN) ? g_indeg[i] : 0;
        s += v[j];
    }
    int incl = s;
    #pragma unroll
    for (int off = 1; off < 32; off <<= 1) {
        int t = __shfl_up_sync(0xffffffff, incl, off);
        if (lane >= off) incl += t;
    }
    if (lane == 31) warpSums[wid] = incl;
    __syncthreads();
    if (wid == 0) {
        int ws = (lane < SCAN_T / 32) ? warpSums[lane] : 0;
        #pragma unroll
        for (int off = 1; off < SCAN_T / 32; off <<= 1) {
            int t = __shfl_up_sync(0xffffffff, ws, off);
            if (lane >= off) ws += t;
        }
        if (lane < SCAN_T / 32) warpSums[lane] = ws;
    }
    __syncthreads();
    int warpOff = (wid > 0) ? warpSums[wid - 1] : 0;
    int run     = warpOff + incl - s;
    #pragma unroll
    for (int j = 0; j < SCAN_I; j++) {
        int i = base + j;
        if (i < NN) g_rowptr[i] = run;
        run += v[j];
    }
    if (tid == SCAN_T - 1) g_blockSums[b] = warpSums[SCAN_T / 32 - 1];
}

__global__ void scanB_kernel() {
    int lane = threadIdx.x;
    int v = (lane < SCAN_B) ? g_blockSums[lane] : 0;
    int incl = v;
    #pragma unroll
    for (int off = 1; off < 32; off <<= 1) {
        int t = __shfl_up_sync(0xffffffff, incl, off);
        if (lane >= off) incl += t;
    }
    if (lane < SCAN_B) g_blockOffs[lane] = incl - v;
    if (lane == 31) g_rowptr[NN] = incl;
}

__global__ void scanC_kernel() {
    int b = blockIdx.x;
    int off = g_blockOffs[b];
    if (off == 0) return;
    int base = b * SCAN_CHUNK + threadIdx.x * SCAN_I;
    #pragma unroll
    for (int j = 0; j < SCAN_I; j++) {
        int i = base + j;
        if (i < NN) g_rowptr[i] += off;
    }
}

__global__ void scatter_kernel(const int* __restrict__ src, const int* __restrict__ dst) {
    int i = blockIdx.x * blockDim.x + threadIdx.x;
    if (i < EE) {
        int d = dst[i];
        int pos = g_rowptr[d] + atomicAdd(&g_cursor[d], 1);
        g_srcsorted[pos] = src[i];
    }
}

// ---------------- aggregation: one warp per node, fp16 rows, fp32 accumulate --------
// Each lane covers 4 features: loads 8 bytes (4 halves) per edge.
__global__ void agg_kernel(const __half* __restrict__ h) {
    int gw = (blockIdx.x * blockDim.x + threadIdx.x) >> 5;
    if (gw >= NN) return;
    int lane = threadIdx.x & 31;
    int beg = g_rowptr[gw], end = g_rowptr[gw + 1];

    float ax = 0.f, ay = 0.f, az = 0.f, aw = 0.f;
    int e = beg;
    for (; e + 4 <= end; e += 4) {
        int s0 = g_srcsorted[e],     s1 = g_srcsorted[e + 1];
        int s2 = g_srcsorted[e + 2], s3 = g_srcsorted[e + 3];
        float w0 = g_outnorm[s0], w1 = g_outnorm[s1];
        float w2 = g_outnorm[s2], w3 = g_outnorm[s3];
        uint2 v0 = *(const uint2*)(h + (size_t)s0 * DD + lane * 4);
        uint2 v1 = *(const uint2*)(h + (size_t)s1 * DD + lane * 4);
        uint2 v2 = *(const uint2*)(h + (size_t)s2 * DD + lane * 4);
        uint2 v3 = *(const uint2*)(h + (size_t)s3 * DD + lane * 4);
        float2 a0 = __half22float2(u_to_h2(v0.x));
        float2 b0 = __half22float2(u_to_h2(v0.y));
        float2 a1 = __half22float2(u_to_h2(v1.x));
        float2 b1 = __half22float2(u_to_h2(v1.y));
        float2 a2 = __half22float2(u_to_h2(v2.x));
        float2 b2 = __half22float2(u_to_h2(v2.y));
        float2 a3 = __half22float2(u_to_h2(v3.x));
        float2 b3 = __half22float2(u_to_h2(v3.y));
        ax += w0 * a0.x; ay += w0 * a0.y; az += w0 * b0.x; aw += w0 * b0.y;
        ax += w1 * a1.x; ay += w1 * a1.y; az += w1 * b1.x; aw += w1 * b1.y;
        ax += w2 * a2.x; ay += w2 * a2.y; az += w2 * b2.x; aw += w2 * b2.y;
        ax += w3 * a3.x; ay += w3 * a3.y; az += w3 * b3.x; aw += w3 * b3.y;
    }
    for (; e < end; e++) {
        int s0 = g_srcsorted[e];
        float w0 = g_outnorm[s0];
        uint2 v0 = *(const uint2*)(h + (size_t)s0 * DD + lane * 4);
        float2 a0 = __half22float2(u_to_h2(v0.x));
        float2 b0 = __half22float2(u_to_h2(v0.y));
        ax += w0 * a0.x; ay += w0 * a0.y; az += w0 * b0.x; aw += w0 * b0.y;
    }
    float s = g_innorm[gw];
    *(float4*)(g_agg + (size_t)gw * DD + lane * 4) =
        make_float4(ax * s, ay * s, az * s, aw * s);
}

// ---------------- SGEMM: C = A @ W + b; A fp32 (g_agg), C fp16 or fp32 -------------
// Block tile 128x128, 256 threads, 8x8 register microkernel, FFMA2.
#define LDSA 132

template <bool OUT_HALF>
__global__ void gemm_kernel(const float* __restrict__ A, const float* __restrict__ W,
                            const float* __restrict__ bias, void* __restrict__ Cv,
                            int M, int doRelu) {
    extern __shared__ float smem[];
    float* As = smem;               // k-major: As[k*LDSA + m]
    float* Bs = smem + 128 * LDSA;  // row-major: Bs[k*128 + n]
    int tid = threadIdx.x;
    int blockM = blockIdx.x * 128;

    {
        int m  = tid >> 1;
        int kh = (tid & 1) * 64;
        int gm = blockM + m;
        bool valid = gm < M;
        const float4* arow = (const float4*)(A + (size_t)gm * DD + kh);
        #pragma unroll
        for (int j = 0; j < 16; j++) {
            float4 v = valid ? arow[j] : make_float4(0.f, 0.f, 0.f, 0.f);
            int k = kh + j * 4;
            As[(k + 0) * LDSA + m] = v.x;
            As[(k + 1) * LDSA + m] = v.y;
            As[(k + 2) * LDSA + m] = v.z;
            As[(k + 3) * LDSA + m] = v.w;
        }
    }
    {
        int nq = tid & 31;
        int kg = tid >> 5;
        #pragma unroll
        for (int r = 0; r < 16; r++) {
            int k = kg * 16 + r;
            *(float4*)(Bs + k * 128 + nq * 4) = *(const float4*)(W + k * 128 + nq * 4);
        }
    }
    __syncthreads();

    int tx = tid & 15, ty = tid >> 4;
    int mBase = ty * 8, nBase = tx * 8;

    unsigned long long acc[8][4];
    const unsigned long long z = pack2(0.f, 0.f);
    #pragma unroll
    for (int i = 0; i < 8; i++)
        #pragma unroll
        for (int jp = 0; jp < 4; jp++) acc[i][jp] = z;

    #pragma unroll 4
    for (int k = 0; k < 128; k++) {
        float4 a0 = *(const float4*)(As + k * LDSA + mBase);
        float4 a1 = *(const float4*)(As + k * LDSA + mBase + 4);
        float4 b0 = *(const float4*)(Bs + k * 128 + nBase);
        float4 b1 = *(const float4*)(Bs + k * 128 + nBase + 4);

        unsigned long long bp[4];
        bp[0] = pack2(b0.x, b0.y);
        bp[1] = pack2(b0.z, b0.w);
        bp[2] = pack2(b1.x, b1.y);
        bp[3] = pack2(b1.z, b1.w);

        float a[8] = {a0.x, a0.y, a0.z, a0.w, a1.x, a1.y, a1.z, a1.w};
        #pragma unroll
        for (int i = 0; i < 8; i++) {
            unsigned long long aa = bcast2(a[i]);
            #pragma unroll
            for (int jp = 0; jp < 4; jp++)
                ffma2(acc[i][jp], aa, bp[jp]);
        }
    }

    float bv[8];
    #pragma unroll
    for (int j = 0; j < 8; j++) bv[j] = bias[nBase + j];

    #pragma unroll
    for (int i = 0; i < 8; i++) {
        int gm = blockM + mBase + i;
        if (gm < M) {
            float o[8];
            #pragma unroll
            for (int jp = 0; jp < 4; jp++) {
                float x, y;
                unpack2(acc[i][jp], x, y);
                o[jp * 2]     = x + bv[jp * 2];
                o[jp * 2 + 1] = y + bv[jp * 2 + 1];
            }
            if (doRelu) {
                #pragma unroll
                for (int j = 0; j < 8; j++) o[j] = fmaxf(o[j], 0.f);
            }
            if (OUT_HALF) {
                __half* C = (__half*)Cv;
                uint4 pk;
                pk.x = h2_to_u(__floats2half2_rn(o[0], o[1]));
                pk.y = h2_to_u(__floats2half2_rn(o[2], o[3]));
                pk.z = h2_to_u(__floats2half2_rn(o[4], o[5]));
                pk.w = h2_to_u(__floats2half2_rn(o[6], o[7]));
                *(uint4*)(C + (size_t)gm * DD + nBase) = pk;
            } else {
                float* C = (float*)Cv;
                *(float4*)(C + (size_t)gm * DD + nBase)     = make_float4(o[0], o[1], o[2], o[3]);
                *(float4*)(C + (size_t)gm * DD + nBase + 4) = make_float4(o[4], o[5], o[6], o[7]);
            }
        }
    }
}

// ---------------- launch ----------------
extern "C" void kernel_launch(void* const* d_in, const int* in_sizes, int n_in,
                              void* d_out, int out_size) {
    const float* h   = (const float*)d_in[0];
    const float* e   = (const float*)d_in[1];
    const int*   src = (const int*)  d_in[2];
    const int*   dst = (const int*)  d_in[3];
    const float* Ws  = (const float*)d_in[4];
    const float* bs  = (const float*)d_in[5];
    float* out = (float*)d_out;

    static cudaStream_t s_side = nullptr;
    static cudaEvent_t  s_fork = nullptr, s_join = nullptr;
    if (!s_side) {
        cudaStreamCreateWithFlags(&s_side, cudaStreamNonBlocking);
        cudaEventCreateWithFlags(&s_fork, cudaEventDisableTiming);
        cudaEventCreateWithFlags(&s_join, cudaEventDisableTiming);
    }

    size_t eElems = (size_t)in_sizes[1];
    int n4 = (int)(eElems / 4);
    const int copyBlocks = 148;          // thin: ~1 block/SM
    bool overlapped = false;
    if (s_side && s_fork && s_join) {
        if (cudaEventRecord(s_fork, 0) == cudaSuccess &&
            cudaStreamWaitEvent(s_side, s_fork, 0) == cudaSuccess) {
            copy_kernel<<<copyBlocks, 256, 0, s_side>>>(
                (const float4*)e, (float4*)(out + (size_t)NN * DD), n4);
            cudaEventRecord(s_join, s_side);
            overlapped = true;
        }
    }
    if (!overlapped) {
        copy_kernel<<<copyBlocks * 6, 256>>>(
            (const float4*)e, (float4*)(out + (size_t)NN * DD), n4);
    }

    const int nb = (NN + 255) / 256;
    const int eb = (EE + 255) / 256;

    __half *h16, *b0, *b1;
    cudaGetSymbolAddress((void**)&h16, g_h16);
    cudaGetSymbolAddress((void**)&b0,  g_b016);
    cudaGetSymbolAddress((void**)&b1,  g_b116);
    float* agg;
    cudaGetSymbolAddress((void**)&agg, g_agg);

    // convert layer-0 input to fp16 (runs while preprocessing proceeds)
    const int nElem = NN * DD;
    convert_kernel<<<(nElem / 4 + 255) / 256, 256>>>(h, h16, nElem);

    zero_kernel<<<nb, 256>>>();
    deg_kernel<<<eb, 256>>>(src, dst);
    norm_kernel<<<nb, 256>>>();
    scanA_kernel<<<SCAN_B, SCAN_T>>>();
    scanB_kernel<<<1, 32>>>();
    scanC_kernel<<<SCAN_B, SCAN_T>>>();
    scatter_kernel<<<eb, 256>>>(src, dst);

    const int SMEM = (128 * LDSA + 128 * 128) * (int)sizeof(float);
    cudaFuncSetAttribute(gemm_kernel<true>,  cudaFuncAttributeMaxDynamicSharedMemorySize, SMEM);
    cudaFuncSetAttribute(gemm_kernel<false>, cudaFuncAttributeMaxDynamicSharedMemorySize, SMEM);

    const int aggBlocks  = (NN * 32 + 255) / 256;
    const int gemmBlocks = (NN + 127) / 128;

    // layer 0: agg(h16) -> gemm -> b0 (fp16, relu)
    agg_kernel<<<aggBlocks, 256>>>(h16);
    gemm_kernel<true><<<gemmBlocks, 256, SMEM>>>(agg, Ws,               bs,          b0, NN, 1);
    // layer 1: agg(b0) -> gemm -> b1 (fp16, relu)
    agg_kernel<<<aggBlocks, 256>>>(b0);
    gemm_kernel<true><<<gemmBlocks, 256, SMEM>>>(agg, Ws + DD * DD,     bs + DD,     b1, NN, 1);
    // layer 2: agg(b1) -> gemm -> out (fp32, no relu)
    agg_kernel<<<aggBlocks, 256>>>(b1);
    gemm_kernel<false><<<gemmBlocks, 256, SMEM>>>(agg, Ws + 2 * DD * DD, bs + 2 * DD, out, NN, 0);

    if (overlapped) cudaStreamWaitEvent(0, s_join, 0);
}

// round 15
// speedup vs baseline: 1.8388x; 1.4193x over previous
#include <cuda_runtime.h>
#include <cuda_fp16.h>

#define NN 50000
#define EE 800000
#define DD 128

// ---------------- scratch (static __device__ arrays; no allocation) ----------------
__device__ __align__(16) __half g_agg16[(size_t)NN * DD];  // agg output (gemm A), fp16
__device__ __align__(16) __half g_h16 [(size_t)NN * DD];   // fp16 copy of layer-0 input
__device__ __align__(16) __half g_b016[(size_t)NN * DD];
__device__ __align__(16) __half g_b116[(size_t)NN * DD];
__device__ __align__(16) __half g_W16 [3 * DD * DD];       // fp16 weights
__device__ float g_outnorm[NN];
__device__ float g_innorm [NN];
__device__ int   g_indeg  [NN];
__device__ int   g_outdeg [NN];
__device__ int   g_cursor [NN];
__device__ int   g_rowptr [NN + 1];
__device__ int   g_srcsorted[EE];

#define SCAN_T 512
#define SCAN_I 4
#define SCAN_CHUNK (SCAN_T * SCAN_I)                       // 2048
#define SCAN_B ((NN + SCAN_CHUNK - 1) / SCAN_CHUNK)        // 25
__device__ int g_blockSums[SCAN_B];
__device__ int g_blockOffs[SCAN_B];

// ---------------- bit-punning helpers for half2 <-> uint ----------------
__device__ __forceinline__ unsigned h2_to_u(__half2 h) {
    return *reinterpret_cast<unsigned*>(&h);
}
__device__ __forceinline__ __half2 u_to_h2(unsigned u) {
    return *reinterpret_cast<__half2*>(&u);
}

// ---------------- tensor-core helpers (mma.sync m16n8k16 f16 -> f32) ----------------
__device__ __forceinline__ void ldsm_x4(unsigned& r0, unsigned& r1, unsigned& r2,
                                        unsigned& r3, unsigned addr) {
    asm volatile("ldmatrix.sync.aligned.m8n8.x4.shared.b16 {%0,%1,%2,%3}, [%4];"
                 : "=r"(r0), "=r"(r1), "=r"(r2), "=r"(r3) : "r"(addr));
}
__device__ __forceinline__ void ldsm_x4_t(unsigned& r0, unsigned& r1, unsigned& r2,
                                          unsigned& r3, unsigned addr) {
    asm volatile("ldmatrix.sync.aligned.m8n8.x4.trans.shared.b16 {%0,%1,%2,%3}, [%4];"
                 : "=r"(r0), "=r"(r1), "=r"(r2), "=r"(r3) : "r"(addr));
}
__device__ __forceinline__ void mma16816(float* c, const unsigned* a,
                                         unsigned b0, unsigned b1) {
    asm volatile("mma.sync.aligned.m16n8k16.row.col.f32.f16.f16.f32 "
                 "{%0,%1,%2,%3}, {%4,%5,%6,%7}, {%8,%9}, {%0,%1,%2,%3};"
                 : "+f"(c[0]), "+f"(c[1]), "+f"(c[2]), "+f"(c[3])
                 : "r"(a[0]), "r"(a[1]), "r"(a[2]), "r"(a[3]), "r"(b0), "r"(b1));
}

// ---------------- thin streaming copy: 1 block/SM, deep MLP, evict-first ----------
#define CPY_UNROLL 16
__global__ void copy_kernel(const float4* __restrict__ src, float4* __restrict__ dst,
                            int n4) {
    int stride = gridDim.x * blockDim.x;
    int i = blockIdx.x * blockDim.x + threadIdx.x;
    int span = stride * CPY_UNROLL;
    for (; i + (CPY_UNROLL - 1) * stride < n4; i += span) {
        float4 v[CPY_UNROLL];
        #pragma unroll
        for (int u = 0; u < CPY_UNROLL; u++) v[u] = __ldcs(src + i + u * stride);
        #pragma unroll
        for (int u = 0; u < CPY_UNROLL; u++) __stcs(dst + i + u * stride, v[u]);
    }
    for (; i < n4; i += stride) __stcs(dst + i, __ldcs(src + i));
}

// ---------------- fp32 -> fp16 converts ----------------
__global__ void convert_kernel(const float* __restrict__ in, __half* __restrict__ out,
                               int n) {
    int i = (blockIdx.x * blockDim.x + threadIdx.x) * 4;
    if (i < n) {
        float4 v = *(const float4*)(in + i);
        __half2 h0 = __floats2half2_rn(v.x, v.y);
        __half2 h1 = __floats2half2_rn(v.z, v.w);
        *(uint2*)(out + i) = make_uint2(h2_to_u(h0), h2_to_u(h1));
    }
}

// ---------------- graph preprocessing ----------------
__global__ void zero_kernel() {
    int i = blockIdx.x * blockDim.x + threadIdx.x;
    if (i < NN) { g_indeg[i] = 0; g_outdeg[i] = 0; g_cursor[i] = 0; }
}

__global__ void deg_kernel(const int* __restrict__ src, const int* __restrict__ dst) {
    int i = blockIdx.x * blockDim.x + threadIdx.x;
    if (i < EE) {
        atomicAdd(&g_outdeg[src[i]], 1);
        atomicAdd(&g_indeg [dst[i]], 1);
    }
}

__global__ void norm_kernel() {
    int i = blockIdx.x * blockDim.x + threadIdx.x;
    if (i < NN) {
        g_outnorm[i] = rsqrtf(fmaxf((float)g_outdeg[i], 1.0f));
        g_innorm [i] = rsqrtf(fmaxf((float)g_indeg [i], 1.0f));
    }
}

// ---- two-level scan ----
__global__ void scanA_kernel() {
    __shared__ int warpSums[SCAN_T / 32];
    int b   = blockIdx.x;
    int tid = threadIdx.x;
    int lane = tid & 31, wid = tid >> 5;
    int base = b * SCAN_CHUNK + tid * SCAN_I;

    int v[SCAN_I];
    int s = 0;
    #pragma unroll
    for (int j = 0; j < SCAN_I; j++) {
        int i = base + j;
        v[j] = (i < NN) ? g_indeg[i] : 0;
        s += v[j];
    }
    int incl = s;
    #pragma unroll
    for (int off = 1; off < 32; off <<= 1) {
        int t = __shfl_up_sync(0xffffffff, incl, off);
        if (lane >= off) incl += t;
    }
    if (lane == 31) warpSums[wid] = incl;
    __syncthreads();
    if (wid == 0) {
        int ws = (lane < SCAN_T / 32) ? warpSums[lane] : 0;
        #pragma unroll
        for (int off = 1; off < SCAN_T / 32; off <<= 1) {
            int t = __shfl_up_sync(0xffffffff, ws, off);
            if (lane >= off) ws += t;
        }
        if (lane < SCAN_T / 32) warpSums[lane] = ws;
    }
    __syncthreads();
    int warpOff = (wid > 0) ? warpSums[wid - 1] : 0;
    int run     = warpOff + incl - s;
    #pragma unroll
    for (int j = 0; j < SCAN_I; j++) {
        int i = base + j;
        if (i < NN) g_rowptr[i] = run;
        run += v[j];
    }
    if (tid == SCAN_T - 1) g_blockSums[b] = warpSums[SCAN_T / 32 - 1];
}

__global__ void scanB_kernel() {
    int lane = threadIdx.x;
    int v = (lane < SCAN_B) ? g_blockSums[lane] : 0;
    int incl = v;
    #pragma unroll
    for (int off = 1; off < 32; off <<= 1) {
        int t = __shfl_up_sync(0xffffffff, incl, off);
        if (lane >= off) incl += t;
    }
    if (lane < SCAN_B) g_blockOffs[lane] = incl - v;
    if (lane == 31) g_rowptr[NN] = incl;
}

__global__ void scanC_kernel() {
    int b = blockIdx.x;
    int off = g_blockOffs[b];
    if (off == 0) return;
    int base = b * SCAN_CHUNK + threadIdx.x * SCAN_I;
    #pragma unroll
    for (int j = 0; j < SCAN_I; j++) {
        int i = base + j;
        if (i < NN) g_rowptr[i] += off;
    }
}

__global__ void scatter_kernel(const int* __restrict__ src, const int* __restrict__ dst) {
    int i = blockIdx.x * blockDim.x + threadIdx.x;
    if (i < EE) {
        int d = dst[i];
        int pos = g_rowptr[d] + atomicAdd(&g_cursor[d], 1);
        g_srcsorted[pos] = src[i];
    }
}

// ---------------- aggregation: one warp per node, fp16 in/out, fp32 accumulate ------
__global__ void agg_kernel(const __half* __restrict__ h) {
    int gw = (blockIdx.x * blockDim.x + threadIdx.x) >> 5;
    if (gw >= NN) return;
    int lane = threadIdx.x & 31;
    int beg = g_rowptr[gw], end = g_rowptr[gw + 1];

    float ax = 0.f, ay = 0.f, az = 0.f, aw = 0.f;
    int e = beg;
    for (; e + 4 <= end; e += 4) {
        int s0 = g_srcsorted[e],     s1 = g_srcsorted[e + 1];
        int s2 = g_srcsorted[e + 2], s3 = g_srcsorted[e + 3];
        float w0 = g_outnorm[s0], w1 = g_outnorm[s1];
        float w2 = g_outnorm[s2], w3 = g_outnorm[s3];
        uint2 v0 = *(const uint2*)(h + (size_t)s0 * DD + lane * 4);
        uint2 v1 = *(const uint2*)(h + (size_t)s1 * DD + lane * 4);
        uint2 v2 = *(const uint2*)(h + (size_t)s2 * DD + lane * 4);
        uint2 v3 = *(const uint2*)(h + (size_t)s3 * DD + lane * 4);
        float2 a0 = __half22float2(u_to_h2(v0.x));
        float2 b0 = __half22float2(u_to_h2(v0.y));
        float2 a1 = __half22float2(u_to_h2(v1.x));
        float2 b1 = __half22float2(u_to_h2(v1.y));
        float2 a2 = __half22float2(u_to_h2(v2.x));
        float2 b2 = __half22float2(u_to_h2(v2.y));
        float2 a3 = __half22float2(u_to_h2(v3.x));
        float2 b3 = __half22float2(u_to_h2(v3.y));
        ax += w0 * a0.x; ay += w0 * a0.y; az += w0 * b0.x; aw += w0 * b0.y;
        ax += w1 * a1.x; ay += w1 * a1.y; az += w1 * b1.x; aw += w1 * b1.y;
        ax += w2 * a2.x; ay += w2 * a2.y; az += w2 * b2.x; aw += w2 * b2.y;
        ax += w3 * a3.x; ay += w3 * a3.y; az += w3 * b3.x; aw += w3 * b3.y;
    }
    for (; e < end; e++) {
        int s0 = g_srcsorted[e];
        float w0 = g_outnorm[s0];
        uint2 v0 = *(const uint2*)(h + (size_t)s0 * DD + lane * 4);
        float2 a0 = __half22float2(u_to_h2(v0.x));
        float2 b0 = __half22float2(u_to_h2(v0.y));
        ax += w0 * a0.x; ay += w0 * a0.y; az += w0 * b0.x; aw += w0 * b0.y;
    }
    float s = g_innorm[gw];
    uint2 pk;
    pk.x = h2_to_u(__floats2half2_rn(ax * s, ay * s));
    pk.y = h2_to_u(__floats2half2_rn(az * s, aw * s));
    *(uint2*)(g_agg16 + (size_t)gw * DD + lane * 4) = pk;
}

// ---------------- tensor-core GEMM: C = A @ W + b; A,W fp16, accum fp32 -------------
// Block 128x128 tile, 256 threads (8 warps, 16 m-rows each), mma.sync m16n8k16.
#define LDA 136   // halves per smem row: 272B stride -> conflict-free ldmatrix

template <bool OUT_HALF>
__global__ void gemmT_kernel(const __half* __restrict__ A, const __half* __restrict__ W,
                             const float* __restrict__ bias, void* __restrict__ Cv,
                             int M, int doRelu) {
    extern __shared__ __half sh[];
    __half* As = sh;                 // 128 x LDA
    __half* Bs = sh + 128 * LDA;     // 128 x LDA (rows = k, cols = n)
    int tid = threadIdx.x;
    int warp = tid >> 5, lane = tid & 31;
    int blockM = blockIdx.x * 128;

    // load A tile (rows m, cols k), guard M
    #pragma unroll
    for (int t = tid; t < 128 * 16; t += 256) {
        int r = t >> 4, c8 = (t & 15) * 8;
        int gm = blockM + r;
        uint4 v = make_uint4(0u, 0u, 0u, 0u);
        if (gm < M) v = *(const uint4*)(A + (size_t)gm * DD + c8);
        *(uint4*)(As + r * LDA + c8) = v;
    }
    // load W tile (rows k, cols n)
    #pragma unroll
    for (int t = tid; t < 128 * 16; t += 256) {
        int r = t >> 4, c8 = (t & 15) * 8;
        *(uint4*)(Bs + r * LDA + c8) = *(const uint4*)(W + r * DD + c8);
    }
    __syncthreads();

    unsigned aBase = (unsigned)__cvta_generic_to_shared(As);
    unsigned bBase = (unsigned)__cvta_generic_to_shared(Bs);

    float acc[16][4];
    #pragma unroll
    for (int j = 0; j < 16; j++)
        #pragma unroll
        for (int q = 0; q < 4; q++) acc[j][q] = 0.f;

    int warpM = warp * 16;
    #pragma unroll
    for (int ks = 0; ks < 8; ks++) {
        int k0 = ks * 16;
        // A fragment: lanes 0-7 m0-7/k0-7, 8-15 m8-15/k0-7, 16-23 m0-7/k8-15, 24-31 m8-15/k8-15
        int ar = warpM + (lane & 7) + ((lane & 8) ? 8 : 0);
        int ac = k0 + ((lane & 16) ? 8 : 0);
        unsigned a[4];
        ldsm_x4(a[0], a[1], a[2], a[3], aBase + (unsigned)(ar * LDA + ac) * 2u);

        #pragma unroll
        for (int np = 0; np < 8; np++) {
            // B 16x16 region (k0..k0+15) x (np*16..np*16+15), trans load
            int br = k0 + (lane & 7) + ((lane & 8) ? 8 : 0);
            int bc = np * 16 + ((lane & 16) ? 8 : 0);
            unsigned b0, b1, b2, b3;
            ldsm_x4_t(b0, b1, b2, b3, bBase + (unsigned)(br * LDA + bc) * 2u);
            mma16816(acc[np * 2],     a, b0, b1);
            mma16816(acc[np * 2 + 1], a, b2, b3);
        }
    }

    // epilogue: lane g=lane>>2 -> rows {g, g+8}; tg=lane&3 -> cols {2tg, 2tg+1}
    int g  = lane >> 2;
    int tg = lane & 3;
    #pragma unroll
    for (int j = 0; j < 16; j++) {
        int col = j * 8 + tg * 2;
        float bv0 = bias[col], bv1 = bias[col + 1];
        #pragma unroll
        for (int half_ = 0; half_ < 2; half_++) {
            int gm = blockM + warpM + g + half_ * 8;
            if (gm < M) {
                float c0 = acc[j][half_ * 2]     + bv0;
                float c1 = acc[j][half_ * 2 + 1] + bv1;
                if (doRelu) { c0 = fmaxf(c0, 0.f); c1 = fmaxf(c1, 0.f); }
                if (OUT_HALF) {
                    __half* C = (__half*)Cv;
                    *(unsigned*)(C + (size_t)gm * DD + col) =
                        h2_to_u(__floats2half2_rn(c0, c1));
                } else {
                    float* C = (float*)Cv;
                    *(float2*)(C + (size_t)gm * DD + col) = make_float2(c0, c1);
                }
            }
        }
    }
}

// ---------------- launch ----------------
extern "C" void kernel_launch(void* const* d_in, const int* in_sizes, int n_in,
                              void* d_out, int out_size) {
    const float* h   = (const float*)d_in[0];
    const float* e   = (const float*)d_in[1];
    const int*   src = (const int*)  d_in[2];
    const int*   dst = (const int*)  d_in[3];
    const float* Ws  = (const float*)d_in[4];
    const float* bs  = (const float*)d_in[5];
    float* out = (float*)d_out;

    static cudaStream_t s_side = nullptr;
    static cudaEvent_t  s_fork = nullptr, s_join = nullptr;
    if (!s_side) {
        cudaStreamCreateWithFlags(&s_side, cudaStreamNonBlocking);
        cudaEventCreateWithFlags(&s_fork, cudaEventDisableTiming);
        cudaEventCreateWithFlags(&s_join, cudaEventDisableTiming);
    }

    size_t eElems = (size_t)in_sizes[1];
    int n4 = (int)(eElems / 4);
    const int copyBlocks = 148;          // thin: ~1 block/SM
    bool overlapped = false;
    if (s_side && s_fork && s_join) {
        if (cudaEventRecord(s_fork, 0) == cudaSuccess &&
            cudaStreamWaitEvent(s_side, s_fork, 0) == cudaSuccess) {
            copy_kernel<<<copyBlocks, 256, 0, s_side>>>(
                (const float4*)e, (float4*)(out + (size_t)NN * DD), n4);
            cudaEventRecord(s_join, s_side);
            overlapped = true;
        }
    }
    if (!overlapped) {
        copy_kernel<<<copyBlocks * 6, 256>>>(
            (const float4*)e, (float4*)(out + (size_t)NN * DD), n4);
    }

    const int nb = (NN + 255) / 256;
    const int eb = (EE + 255) / 256;

    __half *h16, *b0, *b1, *agg16, *w16;
    cudaGetSymbolAddress((void**)&h16,   g_h16);
    cudaGetSymbolAddress((void**)&b0,    g_b016);
    cudaGetSymbolAddress((void**)&b1,    g_b116);
    cudaGetSymbolAddress((void**)&agg16, g_agg16);
    cudaGetSymbolAddress((void**)&w16,   g_W16);

    // converts (overlap with preprocessing chain)
    const int nElem = NN * DD;
    convert_kernel<<<(nElem / 4 + 255) / 256, 256>>>(h, h16, nElem);
    convert_kernel<<<(3 * DD * DD / 4 + 255) / 256, 256>>>(Ws, w16, 3 * DD * DD);

    zero_kernel<<<nb, 256>>>();
    deg_kernel<<<eb, 256>>>(src, dst);
    norm_kernel<<<nb, 256>>>();
    scanA_kernel<<<SCAN_B, SCAN_T>>>();
    scanB_kernel<<<1, 32>>>();
    scanC_kernel<<<SCAN_B, SCAN_T>>>();
    scatter_kernel<<<eb, 256>>>(src, dst);

    const int SMEM = 2 * 128 * LDA * (int)sizeof(__half);   // 69,632 B
    cudaFuncSetAttribute(gemmT_kernel<true>,  cudaFuncAttributeMaxDynamicSharedMemorySize, SMEM);
    cudaFuncSetAttribute(gemmT_kernel<false>, cudaFuncAttributeMaxDynamicSharedMemorySize, SMEM);

    const int aggBlocks  = (NN * 32 + 255) / 256;
    const int gemmBlocks = (NN + 127) / 128;

    // layer 0: agg(h16) -> gemmT -> b0 (fp16, relu)
    agg_kernel<<<aggBlocks, 256>>>(h16);
    gemmT_kernel<true><<<gemmBlocks, 256, SMEM>>>(agg16, w16,               bs,          b0, NN, 1);
    // layer 1
    agg_kernel<<<aggBlocks, 256>>>(b0);
    gemmT_kernel<true><<<gemmBlocks, 256, SMEM>>>(agg16, w16 + DD * DD,     bs + DD,     b1, NN, 1);
    // layer 2 (fp32 out, no relu)
    agg_kernel<<<aggBlocks, 256>>>(b1);
    gemmT_kernel<false><<<gemmBlocks, 256, SMEM>>>(agg16, w16 + 2 * DD * DD, bs + 2 * DD, out, NN, 0);

    if (overlapped) cudaStreamWaitEvent(0, s_join, 0);
}

// round 16
// speedup vs baseline: 1.9374x; 1.0536x over previous
#include <cuda_runtime.h>
#include <cuda_fp16.h>

#define NN 50000
#define EE 800000
#define DD 128

// ---------------- scratch (static __device__ arrays; no allocation) ----------------
__device__ __align__(16) __half g_agg16[(size_t)NN * DD];  // agg output (gemm A), fp16
__device__ __align__(16) __half g_h16 [(size_t)NN * DD];   // fp16, PRE-SCALED by out_norm
__device__ __align__(16) __half g_b016[(size_t)NN * DD];   // layer outs, PRE-SCALED
__device__ __align__(16) __half g_b116[(size_t)NN * DD];
__device__ __align__(16) __half g_W16 [3 * DD * DD];       // fp16 weights
__device__ float g_outnorm[NN];
__device__ float g_innorm [NN];
__device__ int   g_indeg  [NN];
__device__ int   g_outdeg [NN];
__device__ int   g_cursor [NN];
__device__ int   g_rowptr [NN + 1];
__device__ int   g_srcsorted[EE];

#define SCAN_T 512
#define SCAN_I 4
#define SCAN_CHUNK (SCAN_T * SCAN_I)                       // 2048
#define SCAN_B ((NN + SCAN_CHUNK - 1) / SCAN_CHUNK)        // 25
__device__ int g_blockSums[SCAN_B];
__device__ int g_blockOffs[SCAN_B];

// ---------------- bit-punning helpers for half2 <-> uint ----------------
__device__ __forceinline__ unsigned h2_to_u(__half2 h) {
    return *reinterpret_cast<unsigned*>(&h);
}
__device__ __forceinline__ __half2 u_to_h2(unsigned u) {
    return *reinterpret_cast<__half2*>(&u);
}

// ---------------- tensor-core helpers (mma.sync m16n8k16 f16 -> f32) ----------------
__device__ __forceinline__ void ldsm_x4(unsigned& r0, unsigned& r1, unsigned& r2,
                                        unsigned& r3, unsigned addr) {
    asm volatile("ldmatrix.sync.aligned.m8n8.x4.shared.b16 {%0,%1,%2,%3}, [%4];"
                 : "=r"(r0), "=r"(r1), "=r"(r2), "=r"(r3) : "r"(addr));
}
__device__ __forceinline__ void ldsm_x4_t(unsigned& r0, unsigned& r1, unsigned& r2,
                                          unsigned& r3, unsigned addr) {
    asm volatile("ldmatrix.sync.aligned.m8n8.x4.trans.shared.b16 {%0,%1,%2,%3}, [%4];"
                 : "=r"(r0), "=r"(r1), "=r"(r2), "=r"(r3) : "r"(addr));
}
__device__ __forceinline__ void mma16816(float* c, const unsigned* a,
                                         unsigned b0, unsigned b1) {
    asm volatile("mma.sync.aligned.m16n8k16.row.col.f32.f16.f16.f32 "
                 "{%0,%1,%2,%3}, {%4,%5,%6,%7}, {%8,%9}, {%0,%1,%2,%3};"
                 : "+f"(c[0]), "+f"(c[1]), "+f"(c[2]), "+f"(c[3])
                 : "r"(a[0]), "r"(a[1]), "r"(a[2]), "r"(a[3]), "r"(b0), "r"(b1));
}

// ---------------- thin streaming copy: 1 block/SM, deep MLP, evict-first ----------
#define CPY_UNROLL 16
__global__ void copy_kernel(const float4* __restrict__ src, float4* __restrict__ dst,
                            int n4) {
    int stride = gridDim.x * blockDim.x;
    int i = blockIdx.x * blockDim.x + threadIdx.x;
    int span = stride * CPY_UNROLL;
    for (; i + (CPY_UNROLL - 1) * stride < n4; i += span) {
        float4 v[CPY_UNROLL];
        #pragma unroll
        for (int u = 0; u < CPY_UNROLL; u++) v[u] = __ldcs(src + i + u * stride);
        #pragma unroll
        for (int u = 0; u < CPY_UNROLL; u++) __stcs(dst + i + u * stride, v[u]);
    }
    for (; i < n4; i += stride) __stcs(dst + i, __ldcs(src + i));
}

// ---------------- fp32 -> fp16 converts ----------------
__global__ void convert_kernel(const float* __restrict__ in, __half* __restrict__ out,
                               int n) {
    int i = (blockIdx.x * blockDim.x + threadIdx.x) * 4;
    if (i < n) {
        float4 v = *(const float4*)(in + i);
        __half2 h0 = __floats2half2_rn(v.x, v.y);
        __half2 h1 = __floats2half2_rn(v.z, v.w);
        *(uint2*)(out + i) = make_uint2(h2_to_u(h0), h2_to_u(h1));
    }
}

// convert + multiply each row by out_norm[row] (row = i / DD)
__global__ void convert_scale_kernel(const float* __restrict__ in,
                                     __half* __restrict__ out, int n) {
    int i = (blockIdx.x * blockDim.x + threadIdx.x) * 4;
    if (i < n) {
        float s = g_outnorm[i >> 7];   // DD = 128
        float4 v = *(const float4*)(in + i);
        __half2 h0 = __floats2half2_rn(v.x * s, v.y * s);
        __half2 h1 = __floats2half2_rn(v.z * s, v.w * s);
        *(uint2*)(out + i) = make_uint2(h2_to_u(h0), h2_to_u(h1));
    }
}

// ---------------- graph preprocessing ----------------
__global__ void zero_kernel() {
    int i = blockIdx.x * blockDim.x + threadIdx.x;
    if (i < NN) { g_indeg[i] = 0; g_outdeg[i] = 0; g_cursor[i] = 0; }
}

__global__ void deg_kernel(const int* __restrict__ src, const int* __restrict__ dst) {
    int i = blockIdx.x * blockDim.x + threadIdx.x;
    if (i < EE) {
        atomicAdd(&g_outdeg[src[i]], 1);
        atomicAdd(&g_indeg [dst[i]], 1);
    }
}

__global__ void norm_kernel() {
    int i = blockIdx.x * blockDim.x + threadIdx.x;
    if (i < NN) {
        g_outnorm[i] = rsqrtf(fmaxf((float)g_outdeg[i], 1.0f));
        g_innorm [i] = rsqrtf(fmaxf((float)g_indeg [i], 1.0f));
    }
}

// ---- two-level scan ----
__global__ void scanA_kernel() {
    __shared__ int warpSums[SCAN_T / 32];
    int b   = blockIdx.x;
    int tid = threadIdx.x;
    int lane = tid & 31, wid = tid >> 5;
    int base = b * SCAN_CHUNK + tid * SCAN_I;

    int v[SCAN_I];
    int s = 0;
    #pragma unroll
    for (int j = 0; j < SCAN_I; j++) {
        int i = base + j;
        v[j] = (i < NN) ? g_indeg[i] : 0;
        s += v[j];
    }
    int incl = s;
    #pragma unroll
    for (int off = 1; off < 32; off <<= 1) {
        int t = __shfl_up_sync(0xffffffff, incl, off);
        if (lane >= off) incl += t;
    }
    if (lane == 31) warpSums[wid] = incl;
    __syncthreads();
    if (wid == 0) {
        int ws = (lane < SCAN_T / 32) ? warpSums[lane] : 0;
        #pragma unroll
        for (int off = 1; off < SCAN_T / 32; off <<= 1) {
            int t = __shfl_up_sync(0xffffffff, ws, off);
            if (lane >= off) ws += t;
        }
        if (lane < SCAN_T / 32) warpSums[lane] = ws;
    }
    __syncthreads();
    int warpOff = (wid > 0) ? warpSums[wid - 1] : 0;
    int run     = warpOff + incl - s;
    #pragma unroll
    for (int j = 0; j < SCAN_I; j++) {
        int i = base + j;
        if (i < NN) g_rowptr[i] = run;
        run += v[j];
    }
    if (tid == SCAN_T - 1) g_blockSums[b] = warpSums[SCAN_T / 32 - 1];
}

__global__ void scanB_kernel() {
    int lane = threadIdx.x;
    int v = (lane < SCAN_B) ? g_blockSums[lane] : 0;
    int incl = v;
    #pragma unroll
    for (int off = 1; off < 32; off <<= 1) {
        int t = __shfl_up_sync(0xffffffff, incl, off);
        if (lane >= off) incl += t;
    }
    if (lane < SCAN_B) g_blockOffs[lane] = incl - v;
    if (lane == 31) g_rowptr[NN] = incl;
}

__global__ void scanC_kernel() {
    int b = blockIdx.x;
    int off = g_blockOffs[b];
    if (off == 0) return;
    int base = b * SCAN_CHUNK + threadIdx.x * SCAN_I;
    #pragma unroll
    for (int j = 0; j < SCAN_I; j++) {
        int i = base + j;
        if (i < NN) g_rowptr[i] += off;
    }
}

__global__ void scatter_kernel(const int* __restrict__ src, const int* __restrict__ dst) {
    int i = blockIdx.x * blockDim.x + threadIdx.x;
    if (i < EE) {
        int d = dst[i];
        int pos = g_rowptr[d] + atomicAdd(&g_cursor[d], 1);
        g_srcsorted[pos] = src[i];
    }
}

// ---------------- aggregation: one warp per node; rows pre-scaled; pure row-sum -----
__global__ void agg_kernel(const __half* __restrict__ h) {
    int gw = (blockIdx.x * blockDim.x + threadIdx.x) >> 5;
    if (gw >= NN) return;
    int lane = threadIdx.x & 31;
    int beg = g_rowptr[gw], end = g_rowptr[gw + 1];

    float ax = 0.f, ay = 0.f, az = 0.f, aw = 0.f;
    int e = beg;
    for (; e + 8 <= end; e += 8) {
        uint2 v[8];
        #pragma unroll
        for (int u = 0; u < 8; u++) {
            int s = g_srcsorted[e + u];
            v[u] = *(const uint2*)(h + (size_t)s * DD + lane * 4);
        }
        #pragma unroll
        for (int u = 0; u < 8; u++) {
            float2 p = __half22float2(u_to_h2(v[u].x));
            float2 q = __half22float2(u_to_h2(v[u].y));
            ax += p.x; ay += p.y; az += q.x; aw += q.y;
        }
    }
    for (; e < end; e++) {
        int s = g_srcsorted[e];
        uint2 v0 = *(const uint2*)(h + (size_t)s * DD + lane * 4);
        float2 p = __half22float2(u_to_h2(v0.x));
        float2 q = __half22float2(u_to_h2(v0.y));
        ax += p.x; ay += p.y; az += q.x; aw += q.y;
    }
    float s = g_innorm[gw];
    uint2 pk;
    pk.x = h2_to_u(__floats2half2_rn(ax * s, ay * s));
    pk.y = h2_to_u(__floats2half2_rn(az * s, aw * s));
    *(uint2*)(g_agg16 + (size_t)gw * DD + lane * 4) = pk;
}

// ---------------- tensor-core GEMM: C = A @ W + b; A,W fp16, accum fp32 -------------
// Block 128x128 tile, 256 threads (8 warps, 16 m-rows each), mma.sync m16n8k16.
// OUT_HALF outputs are pre-scaled by out_norm[row] (they feed the next gather).
#define LDA 136   // halves per smem row: 272B stride -> conflict-free ldmatrix

template <bool OUT_HALF>
__global__ void gemmT_kernel(const __half* __restrict__ A, const __half* __restrict__ W,
                             const float* __restrict__ bias, void* __restrict__ Cv,
                             int M, int doRelu) {
    extern __shared__ __half sh[];
    __half* As = sh;                 // 128 x LDA
    __half* Bs = sh + 128 * LDA;     // 128 x LDA (rows = k, cols = n)
    int tid = threadIdx.x;
    int warp = tid >> 5, lane = tid & 31;
    int blockM = blockIdx.x * 128;

    // load A tile (rows m, cols k), guard M
    #pragma unroll
    for (int t = tid; t < 128 * 16; t += 256) {
        int r = t >> 4, c8 = (t & 15) * 8;
        int gm = blockM + r;
        uint4 v = make_uint4(0u, 0u, 0u, 0u);
        if (gm < M) v = *(const uint4*)(A + (size_t)gm * DD + c8);
        *(uint4*)(As + r * LDA + c8) = v;
    }
    // load W tile (rows k, cols n)
    #pragma unroll
    for (int t = tid; t < 128 * 16; t += 256) {
        int r = t >> 4, c8 = (t & 15) * 8;
        *(uint4*)(Bs + r * LDA + c8) = *(const uint4*)(W + r * DD + c8);
    }
    __syncthreads();

    unsigned aBase = (unsigned)__cvta_generic_to_shared(As);
    unsigned bBase = (unsigned)__cvta_generic_to_shared(Bs);

    float acc[16][4];
    #pragma unroll
    for (int j = 0; j < 16; j++)
        #pragma unroll
        for (int q = 0; q < 4; q++) acc[j][q] = 0.f;

    int warpM = warp * 16;
    #pragma unroll
    for (int ks = 0; ks < 8; ks++) {
        int k0 = ks * 16;
        int ar = warpM + (lane & 7) + ((lane & 8) ? 8 : 0);
        int ac = k0 + ((lane & 16) ? 8 : 0);
        unsigned a[4];
        ldsm_x4(a[0], a[1], a[2], a[3], aBase + (unsigned)(ar * LDA + ac) * 2u);

        #pragma unroll
        for (int np = 0; np < 8; np++) {
            int br = k0 + (lane & 7) + ((lane & 8) ? 8 : 0);
            int bc = np * 16 + ((lane & 16) ? 8 : 0);
            unsigned b0, b1, b2, b3;
            ldsm_x4_t(b0, b1, b2, b3, bBase + (unsigned)(br * LDA + bc) * 2u);
            mma16816(acc[np * 2],     a, b0, b1);
            mma16816(acc[np * 2 + 1], a, b2, b3);
        }
    }

    // epilogue: lane g=lane>>2 -> rows {g, g+8}; tg=lane&3 -> cols {2tg, 2tg+1}
    int g  = lane >> 2;
    int tg = lane & 3;
    #pragma unroll
    for (int j = 0; j < 16; j++) {
        int col = j * 8 + tg * 2;
        float bv0 = bias[col], bv1 = bias[col + 1];
        #pragma unroll
        for (int half_ = 0; half_ < 2; half_++) {
            int gm = blockM + warpM + g + half_ * 8;
            if (gm < M) {
                float c0 = acc[j][half_ * 2]     + bv0;
                float c1 = acc[j][half_ * 2 + 1] + bv1;
                if (doRelu) { c0 = fmaxf(c0, 0.f); c1 = fmaxf(c1, 0.f); }
                if (OUT_HALF) {
                    float sc = g_outnorm[gm];     // pre-scale for next layer's gather
                    __half* C = (__half*)Cv;
                    *(unsigned*)(C + (size_t)gm * DD + col) =
                        h2_to_u(__floats2half2_rn(c0 * sc, c1 * sc));
                } else {
                    float* C = (float*)Cv;
                    *(float2*)(C + (size_t)gm * DD + col) = make_float2(c0, c1);
                }
            }
        }
    }
}

// ---------------- launch ----------------
extern "C" void kernel_launch(void* const* d_in, const int* in_sizes, int n_in,
                              void* d_out, int out_size) {
    const float* h   = (const float*)d_in[0];
    const float* e   = (const float*)d_in[1];
    const int*   src = (const int*)  d_in[2];
    const int*   dst = (const int*)  d_in[3];
    const float* Ws  = (const float*)d_in[4];
    const float* bs  = (const float*)d_in[5];
    float* out = (float*)d_out;

    static cudaStream_t s_side = nullptr;
    static cudaEvent_t  s_fork = nullptr, s_join = nullptr;
    if (!s_side) {
        cudaStreamCreateWithFlags(&s_side, cudaStreamNonBlocking);
        cudaEventCreateWithFlags(&s_fork, cudaEventDisableTiming);
        cudaEventCreateWithFlags(&s_join, cudaEventDisableTiming);
    }

    size_t eElems = (size_t)in_sizes[1];
    int n4 = (int)(eElems / 4);
    const int copyBlocks = 148;          // thin: ~1 block/SM
    bool overlapped = false;
    if (s_side && s_fork && s_join) {
        if (cudaEventRecord(s_fork, 0) == cudaSuccess &&
            cudaStreamWaitEvent(s_side, s_fork, 0) == cudaSuccess) {
            copy_kernel<<<copyBlocks, 256, 0, s_side>>>(
                (const float4*)e, (float4*)(out + (size_t)NN * DD), n4);
            cudaEventRecord(s_join, s_side);
            overlapped = true;
        }
    }
    if (!overlapped) {
        copy_kernel<<<copyBlocks * 6, 256>>>(
            (const float4*)e, (float4*)(out + (size_t)NN * DD), n4);
    }

    const int nb = (NN + 255) / 256;
    const int eb = (EE + 255) / 256;

    __half *h16, *b0, *b1, *agg16, *w16;
    cudaGetSymbolAddress((void**)&h16,   g_h16);
    cudaGetSymbolAddress((void**)&b0,    g_b016);
    cudaGetSymbolAddress((void**)&b1,    g_b116);
    cudaGetSymbolAddress((void**)&agg16, g_agg16);
    cudaGetSymbolAddress((void**)&w16,   g_W16);

    // W convert has no deps — run first
    convert_kernel<<<(3 * DD * DD / 4 + 255) / 256, 256>>>(Ws, w16, 3 * DD * DD);

    zero_kernel<<<nb, 256>>>();
    deg_kernel<<<eb, 256>>>(src, dst);
    norm_kernel<<<nb, 256>>>();
    // h16 convert needs out_norm (pre-scaled rows) — after norm_kernel
    const int nElem = NN * DD;
    convert_scale_kernel<<<(nElem / 4 + 255) / 256, 256>>>(h, h16, nElem);
    scanA_kernel<<<SCAN_B, SCAN_T>>>();
    scanB_kernel<<<1, 32>>>();
    scanC_kernel<<<SCAN_B, SCAN_T>>>();
    scatter_kernel<<<eb, 256>>>(src, dst);

    const int SMEM = 2 * 128 * LDA * (int)sizeof(__half);   // 69,632 B
    cudaFuncSetAttribute(gemmT_kernel<true>,  cudaFuncAttributeMaxDynamicSharedMemorySize, SMEM);
    cudaFuncSetAttribute(gemmT_kernel<false>, cudaFuncAttributeMaxDynamicSharedMemorySize, SMEM);

    const int aggBlocks  = (NN * 32 + 255) / 256;
    const int gemmBlocks = (NN + 127) / 128;

    // layer 0: agg(h16) -> gemmT -> b0 (fp16, relu, pre-scaled)
    agg_kernel<<<aggBlocks, 256>>>(h16);
    gemmT_kernel<true><<<gemmBlocks, 256, SMEM>>>(agg16, w16,               bs,          b0, NN, 1);
    // layer 1
    agg_kernel<<<aggBlocks, 256>>>(b0);
    gemmT_kernel<true><<<gemmBlocks, 256, SMEM>>>(agg16, w16 + DD * DD,     bs + DD,     b1, NN, 1);
    // layer 2 (fp32 out, no relu, unscaled)
    agg_kernel<<<aggBlocks, 256>>>(b1);
    gemmT_kernel<false><<<gemmBlocks, 256, SMEM>>>(agg16, w16 + 2 * DD * DD, bs + 2 * DD, out, NN, 0);

    if (overlapped) cudaStreamWaitEvent(0, s_join, 0);
}